// round 1
// baseline (speedup 1.0000x reference)
#include <cuda_runtime.h>

// Problem constants
#define Bb 2
#define Ts 2048
#define Cc 1024
#define Hh 16
#define Dh 64
#define MROWS (Bb*Ts)   // 4096

// Scratch buffers (allocation-free rule: __device__ globals)
__device__ float g_q[Bb*Hh*Ts*Dh];
__device__ float g_k[Bb*Hh*Ts*Dh];
__device__ float g_v[Bb*Hh*Ts*Dh];
__device__ float g_y[Bb*Ts*Cc];

// ---------------- SGEMM: out = A[M,K] @ W[N,K]^T ----------------
#define BM 128
#define BN 128
#define BK 16
#define TM 8
#define TN 8
// 256 threads = (BM/TM)*(BN/TN)

// MODE 0: A = x, W selected by blockIdx.z (Wk/Wq/Wv), write to g_k/g_q/g_v in [B,H,T,D] layout
// MODE 1: A = g_y, W = W0 (Wp), write to out_final[M,N] + bias
template<int MODE>
__global__ __launch_bounds__(256)
void gemm_kernel(const float* __restrict__ A_in,
                 const float* __restrict__ W0,
                 const float* __restrict__ W1,
                 const float* __restrict__ W2,
                 const float* __restrict__ bias,
                 float* __restrict__ out_final)
{
    const float* A = (MODE == 0) ? A_in : (const float*)g_y;
    const float* W;
    float* out_heads = nullptr;
    if (MODE == 0) {
        if (blockIdx.z == 0)      { W = W0; out_heads = g_k; }
        else if (blockIdx.z == 1) { W = W1; out_heads = g_q; }
        else                      { W = W2; out_heads = g_v; }
    } else {
        W = W0;
    }

    const int tid = threadIdx.x;
    const int bm = blockIdx.y * BM;
    const int bn = blockIdx.x * BN;

    __shared__ float As[BK][BM + 4];
    __shared__ float Bs[BK][BN + 4];

    float acc[TM][TN];
    #pragma unroll
    for (int i = 0; i < TM; ++i)
        #pragma unroll
        for (int j = 0; j < TN; ++j) acc[i][j] = 0.f;

    const int tx = tid & 15;   // 0..15 column group
    const int ty = tid >> 4;   // 0..15 row group

    const int lrow = tid >> 2;          // 0..63
    const int lcol = (tid & 3) << 2;    // 0,4,8,12

    for (int kt = 0; kt < Cc; kt += BK) {
        #pragma unroll
        for (int r = 0; r < BM; r += 64) {
            float4 a4 = *reinterpret_cast<const float4*>(&A[(size_t)(bm + lrow + r) * Cc + kt + lcol]);
            As[lcol + 0][lrow + r] = a4.x;
            As[lcol + 1][lrow + r] = a4.y;
            As[lcol + 2][lrow + r] = a4.z;
            As[lcol + 3][lrow + r] = a4.w;
            float4 w4 = *reinterpret_cast<const float4*>(&W[(size_t)(bn + lrow + r) * Cc + kt + lcol]);
            Bs[lcol + 0][lrow + r] = w4.x;
            Bs[lcol + 1][lrow + r] = w4.y;
            Bs[lcol + 2][lrow + r] = w4.z;
            Bs[lcol + 3][lrow + r] = w4.w;
        }
        __syncthreads();

        #pragma unroll
        for (int k = 0; k < BK; ++k) {
            float ar[TM], br[TN];
            #pragma unroll
            for (int i = 0; i < TM; i += 4)
                *reinterpret_cast<float4*>(&ar[i]) =
                    *reinterpret_cast<const float4*>(&As[k][ty * TM + i]);
            #pragma unroll
            for (int j = 0; j < TN; j += 4)
                *reinterpret_cast<float4*>(&br[j]) =
                    *reinterpret_cast<const float4*>(&Bs[k][tx * TN + j]);
            #pragma unroll
            for (int i = 0; i < TM; ++i)
                #pragma unroll
                for (int j = 0; j < TN; ++j)
                    acc[i][j] += ar[i] * br[j];
        }
        __syncthreads();
    }

    if (MODE == 0) {
        // scatter into [B, H, T, D]
        #pragma unroll
        for (int i = 0; i < TM; ++i) {
            int n = bm + ty * TM + i;
            int b = n >> 11;          // /T
            int t = n & (Ts - 1);
            #pragma unroll
            for (int j = 0; j < TN; ++j) {
                int col = bn + tx * TN + j;
                int h = col >> 6;     // /Dh
                int dd = col & (Dh - 1);
                out_heads[(((size_t)(b * Hh + h) * Ts) + t) * Dh + dd] = acc[i][j];
            }
        }
    } else {
        #pragma unroll
        for (int i = 0; i < TM; ++i) {
            int n = bm + ty * TM + i;
            #pragma unroll
            for (int j4 = 0; j4 < TN / 4; ++j4) {
                int col = bn + tx * TN + j4 * 4;
                float4 bb = *reinterpret_cast<const float4*>(&bias[col]);
                float4 o;
                o.x = acc[i][j4 * 4 + 0] + bb.x;
                o.y = acc[i][j4 * 4 + 1] + bb.y;
                o.z = acc[i][j4 * 4 + 2] + bb.z;
                o.w = acc[i][j4 * 4 + 3] + bb.w;
                *reinterpret_cast<float4*>(&out_final[(size_t)n * Cc + col]) = o;
            }
        }
    }
}

// ---------------- Flash attention (fp32, no mask) ----------------
#define TQ 128
#define TK 32
#define SCALE 0.125f   // 1/sqrt(64)

__global__ __launch_bounds__(128)
void attn_kernel()
{
    const int bh = blockIdx.y;       // 0..B*H-1
    const int qt = blockIdx.x;       // 0..T/TQ-1
    const int tid = threadIdx.x;     // query row within tile

    const float* qb = g_q + (size_t)bh * Ts * Dh;
    const float* kb = g_k + (size_t)bh * Ts * Dh;
    const float* vb = g_v + (size_t)bh * Ts * Dh;

    __shared__ float Ks[TK][Dh];
    __shared__ float Vs[TK][Dh];

    const int qrow = qt * TQ + tid;

    float qr[Dh];
    #pragma unroll
    for (int d4 = 0; d4 < Dh / 4; ++d4) {
        float4 t4 = *reinterpret_cast<const float4*>(&qb[(size_t)qrow * Dh + d4 * 4]);
        qr[d4 * 4 + 0] = t4.x * SCALE;
        qr[d4 * 4 + 1] = t4.y * SCALE;
        qr[d4 * 4 + 2] = t4.z * SCALE;
        qr[d4 * 4 + 3] = t4.w * SCALE;
    }

    float acc[Dh];
    #pragma unroll
    for (int d = 0; d < Dh; ++d) acc[d] = 0.f;
    float mrun = -1e30f;
    float lrun = 0.f;

    for (int kt = 0; kt < Ts; kt += TK) {
        // Cooperative K/V tile load: TK*Dh = 2048 floats = 512 float4 each
        const float4* kg = reinterpret_cast<const float4*>(&kb[(size_t)kt * Dh]);
        const float4* vg = reinterpret_cast<const float4*>(&vb[(size_t)kt * Dh]);
        float4* ksm = reinterpret_cast<float4*>(&Ks[0][0]);
        float4* vsm = reinterpret_cast<float4*>(&Vs[0][0]);
        #pragma unroll
        for (int i = 0; i < 4; ++i) {
            int idx = i * 128 + tid;
            ksm[idx] = kg[idx];
            vsm[idx] = vg[idx];
        }
        __syncthreads();

        float s[TK];
        float mt = mrun;
        #pragma unroll
        for (int j = 0; j < TK; ++j) {
            float s0 = 0.f, s1 = 0.f, s2 = 0.f, s3 = 0.f;
            const float4* kr = reinterpret_cast<const float4*>(&Ks[j][0]);
            #pragma unroll
            for (int d4 = 0; d4 < Dh / 4; ++d4) {
                float4 kk = kr[d4];
                s0 += qr[d4 * 4 + 0] * kk.x;
                s1 += qr[d4 * 4 + 1] * kk.y;
                s2 += qr[d4 * 4 + 2] * kk.z;
                s3 += qr[d4 * 4 + 3] * kk.w;
            }
            s[j] = (s0 + s1) + (s2 + s3);
            mt = fmaxf(mt, s[j]);
        }

        float corr = __expf(mrun - mt);
        lrun *= corr;
        #pragma unroll
        for (int d = 0; d < Dh; ++d) acc[d] *= corr;

        #pragma unroll
        for (int j = 0; j < TK; ++j) {
            float p = __expf(s[j] - mt);
            lrun += p;
            const float4* vr = reinterpret_cast<const float4*>(&Vs[j][0]);
            #pragma unroll
            for (int d4 = 0; d4 < Dh / 4; ++d4) {
                float4 vv = vr[d4];
                acc[d4 * 4 + 0] += p * vv.x;
                acc[d4 * 4 + 1] += p * vv.y;
                acc[d4 * 4 + 2] += p * vv.z;
                acc[d4 * 4 + 3] += p * vv.w;
            }
        }
        mrun = mt;
        __syncthreads();
    }

    const int b = bh / Hh;
    const int h = bh % Hh;
    const float inv = 1.f / lrun;
    #pragma unroll
    for (int d4 = 0; d4 < Dh / 4; ++d4) {
        float4 o;
        o.x = acc[d4 * 4 + 0] * inv;
        o.y = acc[d4 * 4 + 1] * inv;
        o.z = acc[d4 * 4 + 2] * inv;
        o.w = acc[d4 * 4 + 3] * inv;
        *reinterpret_cast<float4*>(&g_y[((size_t)(b * Ts + qrow)) * Cc + h * Dh + d4 * 4]) = o;
    }
}

extern "C" void kernel_launch(void* const* d_in, const int* in_sizes, int n_in,
                              void* d_out, int out_size)
{
    const float* x  = (const float*)d_in[0];
    const float* Wk = (const float*)d_in[1];
    const float* Wq = (const float*)d_in[2];
    const float* Wv = (const float*)d_in[3];
    const float* Wp = (const float*)d_in[4];
    const float* bp = (const float*)d_in[5];
    float* out = (float*)d_out;

    // QKV projections: x[4096,1024] @ W^T, scattered into [B,H,T,D]
    dim3 gridQKV(Cc / BN, MROWS / BM, 3);
    gemm_kernel<0><<<gridQKV, 256>>>(x, Wk, Wq, Wv, nullptr, nullptr);

    // Attention
    dim3 gridAtt(Ts / TQ, Bb * Hh);
    attn_kernel<<<gridAtt, 128>>>();

    // Output projection + bias
    dim3 gridOut(Cc / BN, MROWS / BM);
    gemm_kernel<1><<<gridOut, 256>>>(nullptr, Wp, nullptr, nullptr, bp, out);
}

// round 2
// speedup vs baseline: 2.3154x; 2.3154x over previous
#include <cuda_runtime.h>
#include <cstdint>

// Problem constants
#define Bb 2
#define Ts 2048
#define Cc 1024
#define Hh 16
#define Dh 64
#define MROWS (Bb*Ts)   // 4096
#define SCALE 0.125f    // 1/sqrt(64)

// Scratch (allocation-free rule: __device__ globals)
__device__ float g_q[Bb*Hh*Ts*Dh];
__device__ float g_k[Bb*Hh*Ts*Dh];
__device__ float g_v[Bb*Hh*Ts*Dh];
__device__ float g_y[Bb*Ts*Cc];

__device__ __forceinline__ float to_tf32(float x) {
    uint32_t u;
    asm("cvt.rna.tf32.f32 %0, %1;" : "=r"(u) : "f"(x));
    return __uint_as_float(u);
}

__device__ __forceinline__ void mma_tf32(float* c, const uint32_t* a, const uint32_t* b) {
    asm volatile(
        "mma.sync.aligned.m16n8k8.row.col.f32.tf32.tf32.f32 "
        "{%0,%1,%2,%3}, {%4,%5,%6,%7}, {%8,%9}, {%0,%1,%2,%3};\n"
        : "+f"(c[0]), "+f"(c[1]), "+f"(c[2]), "+f"(c[3])
        : "r"(a[0]), "r"(a[1]), "r"(a[2]), "r"(a[3]), "r"(b[0]), "r"(b[1]));
}

// ---------------- tf32 GEMM: out = A[M,K] @ W[N,K]^T ----------------
// Block tile 128x128, BK=32. 8 warps as 2(M) x 4(N); warp tile 64x32.
// MODE 0: A = x, W by blockIdx.z (Wk/Wq/Wv), scatter to g_k/g_q/g_v [B,H,T,D]
// MODE 1: A = g_y, W = W0 (Wp), out + bias
template<int MODE>
__global__ __launch_bounds__(256)
void gemm_tf32(const float* __restrict__ A_in,
               const float* __restrict__ W0, const float* __restrict__ W1,
               const float* __restrict__ W2, const float* __restrict__ bias,
               float* __restrict__ out_final)
{
    const float* A;
    const float* W;
    float* out_heads = nullptr;
    if (MODE == 0) {
        A = A_in;
        if (blockIdx.z == 0)      { W = W0; out_heads = g_k; }
        else if (blockIdx.z == 1) { W = W1; out_heads = g_q; }
        else                      { W = W2; out_heads = g_v; }
    } else {
        A = (const float*)g_y; W = W0;
    }

    __shared__ float As[128][36];
    __shared__ float Bs[128][36];

    const int tid  = threadIdx.x;
    const int lane = tid & 31;
    const int wid  = tid >> 5;
    const int wm   = wid & 1;     // 2 warps along M
    const int wn   = wid >> 1;    // 4 warps along N
    const int g    = lane >> 2;   // quad group 0..7
    const int qq   = lane & 3;    // thread in quad 0..3

    const int bm = blockIdx.y * 128;
    const int bn = blockIdx.x * 128;

    const int lrow = tid >> 1;          // 0..127
    const int lc   = (tid & 1) * 16;    // 0 or 16

    float acc[4][4][4];
    #pragma unroll
    for (int i = 0; i < 4; ++i)
        #pragma unroll
        for (int j = 0; j < 4; ++j)
            #pragma unroll
            for (int r = 0; r < 4; ++r) acc[i][j][r] = 0.f;

    for (int kt = 0; kt < Cc; kt += 32) {
        #pragma unroll
        for (int i = 0; i < 4; ++i) {
            float4 a4 = *reinterpret_cast<const float4*>(&A[(size_t)(bm + lrow) * Cc + kt + lc + i*4]);
            As[lrow][lc + i*4 + 0] = to_tf32(a4.x);
            As[lrow][lc + i*4 + 1] = to_tf32(a4.y);
            As[lrow][lc + i*4 + 2] = to_tf32(a4.z);
            As[lrow][lc + i*4 + 3] = to_tf32(a4.w);
            float4 w4 = *reinterpret_cast<const float4*>(&W[(size_t)(bn + lrow) * Cc + kt + lc + i*4]);
            Bs[lrow][lc + i*4 + 0] = to_tf32(w4.x);
            Bs[lrow][lc + i*4 + 1] = to_tf32(w4.y);
            Bs[lrow][lc + i*4 + 2] = to_tf32(w4.z);
            Bs[lrow][lc + i*4 + 3] = to_tf32(w4.w);
        }
        __syncthreads();

        #pragma unroll
        for (int ks = 0; ks < 4; ++ks) {
            uint32_t af[4][4];
            uint32_t bf[4][2];
            #pragma unroll
            for (int mi = 0; mi < 4; ++mi) {
                int r = wm * 64 + mi * 16;
                af[mi][0] = __float_as_uint(As[r + g    ][ks*8 + qq    ]);
                af[mi][1] = __float_as_uint(As[r + g + 8][ks*8 + qq    ]);
                af[mi][2] = __float_as_uint(As[r + g    ][ks*8 + qq + 4]);
                af[mi][3] = __float_as_uint(As[r + g + 8][ks*8 + qq + 4]);
            }
            #pragma unroll
            for (int ni = 0; ni < 4; ++ni) {
                int c = wn * 32 + ni * 8;
                bf[ni][0] = __float_as_uint(Bs[c + g][ks*8 + qq    ]);
                bf[ni][1] = __float_as_uint(Bs[c + g][ks*8 + qq + 4]);
            }
            #pragma unroll
            for (int mi = 0; mi < 4; ++mi)
                #pragma unroll
                for (int ni = 0; ni < 4; ++ni)
                    mma_tf32(acc[mi][ni], af[mi], bf[ni]);
        }
        __syncthreads();
    }

    // Epilogue
    #pragma unroll
    for (int mi = 0; mi < 4; ++mi) {
        int r0 = bm + wm * 64 + mi * 16 + g;   // rows r0, r0+8
        #pragma unroll
        for (int ni = 0; ni < 4; ++ni) {
            int c = bn + wn * 32 + ni * 8 + 2 * qq;
            if (MODE == 0) {
                int b0 = r0 >> 11;
                int t0 = r0 & (Ts - 1);
                int t1 = (r0 + 8) & (Ts - 1);
                int h  = c >> 6;
                int dd = c & (Dh - 1);
                float2 v0 = make_float2(acc[mi][ni][0], acc[mi][ni][1]);
                float2 v1 = make_float2(acc[mi][ni][2], acc[mi][ni][3]);
                *reinterpret_cast<float2*>(&out_heads[(((size_t)(b0*Hh + h) * Ts) + t0) * Dh + dd]) = v0;
                *reinterpret_cast<float2*>(&out_heads[(((size_t)(b0*Hh + h) * Ts) + t1) * Dh + dd]) = v1;
            } else {
                float2 bb = *reinterpret_cast<const float2*>(&bias[c]);
                float2 v0 = make_float2(acc[mi][ni][0] + bb.x, acc[mi][ni][1] + bb.y);
                float2 v1 = make_float2(acc[mi][ni][2] + bb.x, acc[mi][ni][3] + bb.y);
                *reinterpret_cast<float2*>(&out_final[(size_t)r0 * Cc + c]) = v0;
                *reinterpret_cast<float2*>(&out_final[(size_t)(r0 + 8) * Cc + c]) = v1;
            }
        }
    }
}

// ---------------- Flash attention with tf32 mma ----------------
// CTA: 64 q-rows, 4 warps, each warp owns 16 q-rows x full 64 kv-cols.
// KV tiles of 64. S = Q K^T via mma; online softmax on C frags;
// P staged through smem (reuses K buffer); O += P V via mma.
__global__ __launch_bounds__(128)
void attn_tf32()
{
    const int bh  = blockIdx.y;    // 0..B*H-1
    const int qt  = blockIdx.x;    // 0..T/64-1
    const int tid = threadIdx.x;
    const int lane = tid & 31;
    const int wid  = tid >> 5;     // 0..3
    const int g    = lane >> 2;
    const int qq   = lane & 3;

    const float* qb = g_q + (size_t)bh * Ts * Dh;
    const float* kb = g_k + (size_t)bh * Ts * Dh;
    const float* vb = g_v + (size_t)bh * Ts * Dh;

    __shared__ float Ks[64][68];   // [s][d] for S-mma B frags; reused as P buffer
    __shared__ float Vt[64][68];   // [d][s] transposed V for PV-mma B frags

    const int q0 = qt * 64 + wid * 16;

    // Q fragments (scaled, tf32), persistent: 8 k-steps x 4 regs
    uint32_t qf[8][4];
    #pragma unroll
    for (int ks = 0; ks < 8; ++ks) {
        qf[ks][0] = __float_as_uint(to_tf32(qb[(size_t)(q0 + g    ) * Dh + ks*8 + qq    ] * SCALE));
        qf[ks][1] = __float_as_uint(to_tf32(qb[(size_t)(q0 + g + 8) * Dh + ks*8 + qq    ] * SCALE));
        qf[ks][2] = __float_as_uint(to_tf32(qb[(size_t)(q0 + g    ) * Dh + ks*8 + qq + 4] * SCALE));
        qf[ks][3] = __float_as_uint(to_tf32(qb[(size_t)(q0 + g + 8) * Dh + ks*8 + qq + 4] * SCALE));
    }

    float o[8][4];
    #pragma unroll
    for (int ni = 0; ni < 8; ++ni)
        #pragma unroll
        for (int r = 0; r < 4; ++r) o[ni][r] = 0.f;
    float m0 = -1e30f, m1 = -1e30f, l0 = 0.f, l1 = 0.f;

    const int lrow = tid >> 1;         // 0..63
    const int lc   = (tid & 1) * 32;   // 0 or 32

    for (int kt = 0; kt < Ts; kt += 64) {
        // Load K tile [64 s][64 d] and V transposed [64 d][64 s]
        #pragma unroll
        for (int i = 0; i < 8; ++i) {
            int c = lc + i * 4;
            float4 k4 = *reinterpret_cast<const float4*>(&kb[(size_t)(kt + lrow) * Dh + c]);
            Ks[lrow][c + 0] = to_tf32(k4.x);
            Ks[lrow][c + 1] = to_tf32(k4.y);
            Ks[lrow][c + 2] = to_tf32(k4.z);
            Ks[lrow][c + 3] = to_tf32(k4.w);
            float4 v4 = *reinterpret_cast<const float4*>(&vb[(size_t)(kt + lrow) * Dh + c]);
            Vt[c + 0][lrow] = to_tf32(v4.x);
            Vt[c + 1][lrow] = to_tf32(v4.y);
            Vt[c + 2][lrow] = to_tf32(v4.z);
            Vt[c + 3][lrow] = to_tf32(v4.w);
        }
        __syncthreads();

        // S = Q K^T  (warp: 16 x 64)
        float s[8][4];
        #pragma unroll
        for (int ni = 0; ni < 8; ++ni)
            #pragma unroll
            for (int r = 0; r < 4; ++r) s[ni][r] = 0.f;

        #pragma unroll
        for (int ks = 0; ks < 8; ++ks) {
            #pragma unroll
            for (int ni = 0; ni < 8; ++ni) {
                uint32_t bfr[2];
                bfr[0] = __float_as_uint(Ks[ni*8 + g][ks*8 + qq    ]);
                bfr[1] = __float_as_uint(Ks[ni*8 + g][ks*8 + qq + 4]);
                mma_tf32(s[ni], qf[ks], bfr);
            }
        }

        // Online softmax (rows g -> regs 0,1 ; g+8 -> regs 2,3)
        float mt0 = m0, mt1 = m1;
        #pragma unroll
        for (int ni = 0; ni < 8; ++ni) {
            mt0 = fmaxf(mt0, fmaxf(s[ni][0], s[ni][1]));
            mt1 = fmaxf(mt1, fmaxf(s[ni][2], s[ni][3]));
        }
        mt0 = fmaxf(mt0, __shfl_xor_sync(0xffffffffu, mt0, 1));
        mt0 = fmaxf(mt0, __shfl_xor_sync(0xffffffffu, mt0, 2));
        mt1 = fmaxf(mt1, __shfl_xor_sync(0xffffffffu, mt1, 1));
        mt1 = fmaxf(mt1, __shfl_xor_sync(0xffffffffu, mt1, 2));

        float corr0 = __expf(m0 - mt0);
        float corr1 = __expf(m1 - mt1);
        m0 = mt0; m1 = mt1;

        __syncthreads();   // all warps done reading Ks as K; safe to reuse as P

        float rs0 = 0.f, rs1 = 0.f;
        #pragma unroll
        for (int ni = 0; ni < 8; ++ni) {
            float p0 = __expf(s[ni][0] - m0);
            float p1 = __expf(s[ni][1] - m0);
            float p2 = __expf(s[ni][2] - m1);
            float p3 = __expf(s[ni][3] - m1);
            rs0 += p0 + p1;
            rs1 += p2 + p3;
            int c = ni * 8 + 2 * qq;
            Ks[wid*16 + g    ][c    ] = to_tf32(p0);
            Ks[wid*16 + g    ][c + 1] = to_tf32(p1);
            Ks[wid*16 + g + 8][c    ] = to_tf32(p2);
            Ks[wid*16 + g + 8][c + 1] = to_tf32(p3);
        }
        rs0 += __shfl_xor_sync(0xffffffffu, rs0, 1);
        rs0 += __shfl_xor_sync(0xffffffffu, rs0, 2);
        rs1 += __shfl_xor_sync(0xffffffffu, rs1, 1);
        rs1 += __shfl_xor_sync(0xffffffffu, rs1, 2);
        l0 = l0 * corr0 + rs0;
        l1 = l1 * corr1 + rs1;

        #pragma unroll
        for (int ni = 0; ni < 8; ++ni) {
            o[ni][0] *= corr0; o[ni][1] *= corr0;
            o[ni][2] *= corr1; o[ni][3] *= corr1;
        }
        __syncwarp();

        // O += P V   (A = P from smem, B = Vt)
        #pragma unroll
        for (int ks = 0; ks < 8; ++ks) {
            uint32_t af[4];
            af[0] = __float_as_uint(Ks[wid*16 + g    ][ks*8 + qq    ]);
            af[1] = __float_as_uint(Ks[wid*16 + g + 8][ks*8 + qq    ]);
            af[2] = __float_as_uint(Ks[wid*16 + g    ][ks*8 + qq + 4]);
            af[3] = __float_as_uint(Ks[wid*16 + g + 8][ks*8 + qq + 4]);
            #pragma unroll
            for (int ni = 0; ni < 8; ++ni) {
                uint32_t bfr[2];
                bfr[0] = __float_as_uint(Vt[ni*8 + g][ks*8 + qq    ]);
                bfr[1] = __float_as_uint(Vt[ni*8 + g][ks*8 + qq + 4]);
                mma_tf32(o[ni], af, bfr);
            }
        }
        __syncthreads();   // protect Ks/Vt before next tile load
    }

    // Write O / l  ->  g_y [b][t][h*64+d]
    const int b = bh / Hh;
    const int h = bh % Hh;
    const float inv0 = 1.f / l0;
    const float inv1 = 1.f / l1;
    const int r0 = q0 + g;
    #pragma unroll
    for (int ni = 0; ni < 8; ++ni) {
        int c = ni * 8 + 2 * qq;
        float2 v0 = make_float2(o[ni][0] * inv0, o[ni][1] * inv0);
        float2 v1 = make_float2(o[ni][2] * inv1, o[ni][3] * inv1);
        *reinterpret_cast<float2*>(&g_y[((size_t)(b * Ts + r0    )) * Cc + h * Dh + c]) = v0;
        *reinterpret_cast<float2*>(&g_y[((size_t)(b * Ts + r0 + 8)) * Cc + h * Dh + c]) = v1;
    }
}

extern "C" void kernel_launch(void* const* d_in, const int* in_sizes, int n_in,
                              void* d_out, int out_size)
{
    const float* x  = (const float*)d_in[0];
    const float* Wk = (const float*)d_in[1];
    const float* Wq = (const float*)d_in[2];
    const float* Wv = (const float*)d_in[3];
    const float* Wp = (const float*)d_in[4];
    const float* bp = (const float*)d_in[5];
    float* out = (float*)d_out;

    dim3 gridQKV(Cc / 128, MROWS / 128, 3);
    gemm_tf32<0><<<gridQKV, 256>>>(x, Wk, Wq, Wv, nullptr, nullptr);

    dim3 gridAtt(Ts / 64, Bb * Hh);
    attn_tf32<<<gridAtt, 128>>>();

    dim3 gridOut(Cc / 128, MROWS / 128);
    gemm_tf32<1><<<gridOut, 256>>>(nullptr, Wp, nullptr, nullptr, bp, out);
}

// round 3
// speedup vs baseline: 2.8739x; 1.2412x over previous
#include <cuda_runtime.h>
#include <cstdint>

// Problem constants
#define Bb 2
#define Ts 2048
#define Cc 1024
#define Hh 16
#define Dh 64
#define MROWS (Bb*Ts)   // 4096
#define SCALE 0.125f    // 1/sqrt(64)

// Scratch (allocation-free rule: __device__ globals)
__device__ float g_q[Bb*Hh*Ts*Dh];
__device__ float g_k[Bb*Hh*Ts*Dh];
__device__ float g_v[Bb*Hh*Ts*Dh];   // V stored TRANSPOSED per head: [b,h][d][t]
__device__ float g_y[Bb*Ts*Cc];

__device__ __forceinline__ float to_tf32(float x) {
    uint32_t u;
    asm("cvt.rna.tf32.f32 %0, %1;" : "=r"(u) : "f"(x));
    return __uint_as_float(u);
}
__device__ __forceinline__ uint32_t fu(float x) { return __float_as_uint(x); }

__device__ __forceinline__ void mma_tf32(float* c, const uint32_t* a, const uint32_t* b) {
    asm volatile(
        "mma.sync.aligned.m16n8k8.row.col.f32.tf32.tf32.f32 "
        "{%0,%1,%2,%3}, {%4,%5,%6,%7}, {%8,%9}, {%0,%1,%2,%3};\n"
        : "+f"(c[0]), "+f"(c[1]), "+f"(c[2]), "+f"(c[3])
        : "r"(a[0]), "r"(a[1]), "r"(a[2]), "r"(a[3]), "r"(b[0]), "r"(b[1]));
}

// smem permutation: element with k-col c (within 32- or 64-wide tile) stored at
//   pos(c) = qq*4 + (ks>>1)*16 + (ks&1)*2 + half   (qq=c&3, half=(c>>2)&1, ks=c>>3)
// then XOR-swizzled by swz(row) = ((row&1)<<4) | ((row&2)<<2).
// Fragment load: float4 at (qq*4 + jj*16)^swz(row) = [ks=2jj:(b0,b1), ks=2jj+1:(b0,b1)]
// (for A rows: [a0,a2] low / [a1,a3] high). All frag loads bank-conflict-free.

// ---------------- tf32 GEMM: out = A[M,K] @ W[N,K]^T ----------------
// Block 128x128, BK=32, 8 warps 2(M)x4(N), warp tile 64x32.
template<int MODE>
__global__ __launch_bounds__(256, 2)
void gemm_tf32(const float* __restrict__ A_in,
               const float* __restrict__ W0, const float* __restrict__ W1,
               const float* __restrict__ W2, const float* __restrict__ bias,
               float* __restrict__ out_final)
{
    const float* A;
    const float* W;
    float* out_heads = nullptr;
    if (MODE == 0) {
        A = A_in;
        if (blockIdx.z == 0)      { W = W0; out_heads = g_k; }
        else if (blockIdx.z == 1) { W = W1; out_heads = g_q; }
        else                      { W = W2; out_heads = g_v; }
    } else {
        A = (const float*)g_y; W = W0;
    }

    __shared__ float As[128][32];
    __shared__ float Bs[128][32];

    const int tid  = threadIdx.x;
    const int lane = tid & 31;
    const int warp = tid >> 5;
    const int wm   = warp & 1;
    const int wn   = warp >> 1;
    const int g    = lane >> 2;
    const int qq   = lane & 3;
    const int bm = blockIdx.y * 128;
    const int bn = blockIdx.x * 128;

    // loader mapping: per warp-iter 4 rows x 32 cols; lane: row=lr, colbase=lcb
    const int lr  = lane >> 3;          // 0..3
    const int l7  = lane & 7;
    const int lcb = l7 * 4;             // 0..28
    const int posBase = ((l7 >> 2) << 4) | (l7 & 3);       // jj*16 + kslow*2 + half
    const int swzl = ((lr & 1) << 4) | ((lr & 2) << 2);    // row&3 == lr
    const int swzg = ((g & 1) << 4) | ((g & 2) << 2);      // frag rows have row&3 == g&3

    float acc[4][4][4];
    #pragma unroll
    for (int i = 0; i < 4; ++i)
        #pragma unroll
        for (int j = 0; j < 4; ++j)
            #pragma unroll
            for (int r = 0; r < 4; ++r) acc[i][j][r] = 0.f;

    for (int kt = 0; kt < Cc; kt += 32) {
        #pragma unroll
        for (int it = 0; it < 4; ++it) {
            int r = warp * 16 + it * 4 + lr;
            float4 a4 = *reinterpret_cast<const float4*>(&A[(size_t)(bm + r) * Cc + kt + lcb]);
            float4 w4 = *reinterpret_cast<const float4*>(&W[(size_t)(bn + r) * Cc + kt + lcb]);
            As[r][(posBase +  0) ^ swzl] = to_tf32(a4.x);
            As[r][(posBase +  4) ^ swzl] = to_tf32(a4.y);
            As[r][(posBase +  8) ^ swzl] = to_tf32(a4.z);
            As[r][(posBase + 12) ^ swzl] = to_tf32(a4.w);
            Bs[r][(posBase +  0) ^ swzl] = to_tf32(w4.x);
            Bs[r][(posBase +  4) ^ swzl] = to_tf32(w4.y);
            Bs[r][(posBase +  8) ^ swzl] = to_tf32(w4.z);
            Bs[r][(posBase + 12) ^ swzl] = to_tf32(w4.w);
        }
        __syncthreads();

        #pragma unroll
        for (int jj = 0; jj < 2; ++jj) {
            const int fc = (qq * 4 + jj * 16) ^ swzg;
            float4 bfr[4];
            #pragma unroll
            for (int ni = 0; ni < 4; ++ni)
                bfr[ni] = *reinterpret_cast<const float4*>(&Bs[wn * 32 + ni * 8 + g][fc]);
            #pragma unroll
            for (int mi = 0; mi < 4; ++mi) {
                float4 alo = *reinterpret_cast<const float4*>(&As[wm * 64 + mi * 16 + g    ][fc]);
                float4 ahi = *reinterpret_cast<const float4*>(&As[wm * 64 + mi * 16 + g + 8][fc]);
                uint32_t a0[4] = {fu(alo.x), fu(ahi.x), fu(alo.y), fu(ahi.y)};  // ks = 2jj
                uint32_t a1[4] = {fu(alo.z), fu(ahi.z), fu(alo.w), fu(ahi.w)};  // ks = 2jj+1
                #pragma unroll
                for (int ni = 0; ni < 4; ++ni) {
                    uint32_t b0[2] = {fu(bfr[ni].x), fu(bfr[ni].y)};
                    uint32_t b1[2] = {fu(bfr[ni].z), fu(bfr[ni].w)};
                    mma_tf32(acc[mi][ni], a0, b0);
                    mma_tf32(acc[mi][ni], a1, b1);
                }
            }
        }
        __syncthreads();
    }

    // Epilogue
    #pragma unroll
    for (int mi = 0; mi < 4; ++mi) {
        int r0 = bm + wm * 64 + mi * 16 + g;   // rows r0, r0+8
        #pragma unroll
        for (int ni = 0; ni < 4; ++ni) {
            int c = bn + wn * 32 + ni * 8 + 2 * qq;
            if (MODE == 0) {
                int b0 = r0 >> 11;
                int t0 = r0 & (Ts - 1);
                int t1 = (r0 + 8) & (Ts - 1);
                int h  = c >> 6;
                int dd = c & (Dh - 1);
                if (blockIdx.z == 2) {
                    // V: store transposed [b,h][d][t]
                    size_t base = ((size_t)(b0 * Hh + h) * Dh);
                    out_heads[(base + dd    ) * Ts + t0] = acc[mi][ni][0];
                    out_heads[(base + dd + 1) * Ts + t0] = acc[mi][ni][1];
                    out_heads[(base + dd    ) * Ts + t1] = acc[mi][ni][2];
                    out_heads[(base + dd + 1) * Ts + t1] = acc[mi][ni][3];
                } else {
                    float2 v0 = make_float2(acc[mi][ni][0], acc[mi][ni][1]);
                    float2 v1 = make_float2(acc[mi][ni][2], acc[mi][ni][3]);
                    *reinterpret_cast<float2*>(&out_heads[(((size_t)(b0*Hh + h) * Ts) + t0) * Dh + dd]) = v0;
                    *reinterpret_cast<float2*>(&out_heads[(((size_t)(b0*Hh + h) * Ts) + t1) * Dh + dd]) = v1;
                }
            } else {
                float2 bb = *reinterpret_cast<const float2*>(&bias[c]);
                float2 v0 = make_float2(acc[mi][ni][0] + bb.x, acc[mi][ni][1] + bb.y);
                float2 v1 = make_float2(acc[mi][ni][2] + bb.x, acc[mi][ni][3] + bb.y);
                *reinterpret_cast<float2*>(&out_final[(size_t)r0 * Cc + c]) = v0;
                *reinterpret_cast<float2*>(&out_final[(size_t)(r0 + 8) * Cc + c]) = v1;
            }
        }
    }
}

// ---------------- Flash attention, tf32 mma, vectorized smem ----------------
__global__ __launch_bounds__(128)
void attn_tf32()
{
    const int bh  = blockIdx.y;
    const int qt  = blockIdx.x;
    const int tid = threadIdx.x;
    const int lane = tid & 31;
    const int wid  = tid >> 5;
    const int g    = lane >> 2;
    const int qq   = lane & 3;

    const float* qb  = g_q + (size_t)bh * Ts * Dh;
    const float* kb  = g_k + (size_t)bh * Ts * Dh;
    const float* vtb = g_v + (size_t)bh * Dh * Ts;   // [d][t]

    __shared__ float Ks[64][64];   // K tile [s][d-perm]; reused as P [q][s-perm]
    __shared__ float Vt[64][64];   // V^T tile [d][s-perm]

    const int swzg = ((g & 1) << 4) | ((g & 2) << 2);
    const int q0 = qt * 64 + wid * 16;

    // Q fragments (scaled, tf32), persistent
    uint32_t qf[8][4];
    #pragma unroll
    for (int ks = 0; ks < 8; ++ks) {
        qf[ks][0] = fu(to_tf32(qb[(size_t)(q0 + g    ) * Dh + ks*8 + qq    ] * SCALE));
        qf[ks][1] = fu(to_tf32(qb[(size_t)(q0 + g + 8) * Dh + ks*8 + qq    ] * SCALE));
        qf[ks][2] = fu(to_tf32(qb[(size_t)(q0 + g    ) * Dh + ks*8 + qq + 4] * SCALE));
        qf[ks][3] = fu(to_tf32(qb[(size_t)(q0 + g + 8) * Dh + ks*8 + qq + 4] * SCALE));
    }

    float o[8][4];
    #pragma unroll
    for (int ni = 0; ni < 8; ++ni)
        #pragma unroll
        for (int r = 0; r < 4; ++r) o[ni][r] = 0.f;
    float m0 = -1e30f, m1 = -1e30f, l0 = 0.f, l1 = 0.f;

    // loader mapping: per iter 8 rows x 64 cols (128 threads x float4)
    const int l15  = tid & 15;
    const int lrow = tid >> 4;            // 0..7
    const int lcb  = l15 * 4;             // 0..60
    const int posB = ((l15 >> 2) << 4) | (l15 & 3);
    const int swzl = ((lrow & 1) << 4) | ((lrow & 2) << 2);

    for (int kt = 0; kt < Ts; kt += 64) {
        #pragma unroll
        for (int it = 0; it < 8; ++it) {
            int r = it * 8 + lrow;
            float4 k4 = *reinterpret_cast<const float4*>(&kb[(size_t)(kt + r) * Dh + lcb]);
            Ks[r][(posB +  0) ^ swzl] = to_tf32(k4.x);
            Ks[r][(posB +  4) ^ swzl] = to_tf32(k4.y);
            Ks[r][(posB +  8) ^ swzl] = to_tf32(k4.z);
            Ks[r][(posB + 12) ^ swzl] = to_tf32(k4.w);
            float4 v4 = *reinterpret_cast<const float4*>(&vtb[(size_t)r * Ts + kt + lcb]);
            Vt[r][(posB +  0) ^ swzl] = to_tf32(v4.x);
            Vt[r][(posB +  4) ^ swzl] = to_tf32(v4.y);
            Vt[r][(posB +  8) ^ swzl] = to_tf32(v4.z);
            Vt[r][(posB + 12) ^ swzl] = to_tf32(v4.w);
        }
        __syncthreads();

        // S = Q K^T  (warp: 16 x 64)
        float s[8][4];
        #pragma unroll
        for (int ni = 0; ni < 8; ++ni)
            #pragma unroll
            for (int r = 0; r < 4; ++r) s[ni][r] = 0.f;

        #pragma unroll
        for (int ni = 0; ni < 8; ++ni) {
            const float* krow = &Ks[ni * 8 + g][0];
            #pragma unroll
            for (int jj = 0; jj < 4; ++jj) {
                float4 b4 = *reinterpret_cast<const float4*>(&krow[(qq * 4 + jj * 16) ^ swzg]);
                uint32_t b0[2] = {fu(b4.x), fu(b4.y)};
                uint32_t b1[2] = {fu(b4.z), fu(b4.w)};
                mma_tf32(s[ni], qf[2*jj    ], b0);
                mma_tf32(s[ni], qf[2*jj + 1], b1);
            }
        }

        // Online softmax
        float mt0 = m0, mt1 = m1;
        #pragma unroll
        for (int ni = 0; ni < 8; ++ni) {
            mt0 = fmaxf(mt0, fmaxf(s[ni][0], s[ni][1]));
            mt1 = fmaxf(mt1, fmaxf(s[ni][2], s[ni][3]));
        }
        mt0 = fmaxf(mt0, __shfl_xor_sync(0xffffffffu, mt0, 1));
        mt0 = fmaxf(mt0, __shfl_xor_sync(0xffffffffu, mt0, 2));
        mt1 = fmaxf(mt1, __shfl_xor_sync(0xffffffffu, mt1, 1));
        mt1 = fmaxf(mt1, __shfl_xor_sync(0xffffffffu, mt1, 2));

        float corr0 = __expf(m0 - mt0);
        float corr1 = __expf(m1 - mt1);
        m0 = mt0; m1 = mt1;

        __syncthreads();   // all warps done reading Ks(K); reuse as P

        float rs0 = 0.f, rs1 = 0.f;
        const int rr0 = 2 * qq, rr1 = 2 * qq + 1;
        const int pc0 = (rr0 & 3) * 4 + (rr0 >> 2);
        const int pc1 = (rr1 & 3) * 4 + (rr1 >> 2);
        #pragma unroll
        for (int ni = 0; ni < 8; ++ni) {
            float p0 = __expf(s[ni][0] - m0);
            float p1 = __expf(s[ni][1] - m0);
            float p2 = __expf(s[ni][2] - m1);
            float p3 = __expf(s[ni][3] - m1);
            rs0 += p0 + p1;
            rs1 += p2 + p3;
            int base_n = ((ni >> 1) << 4) | ((ni & 1) << 1);
            int c0 = (base_n + pc0) ^ swzg;
            int c1 = (base_n + pc1) ^ swzg;
            Ks[wid*16 + g    ][c0] = to_tf32(p0);
            Ks[wid*16 + g    ][c1] = to_tf32(p1);
            Ks[wid*16 + g + 8][c0] = to_tf32(p2);
            Ks[wid*16 + g + 8][c1] = to_tf32(p3);
        }
        rs0 += __shfl_xor_sync(0xffffffffu, rs0, 1);
        rs0 += __shfl_xor_sync(0xffffffffu, rs0, 2);
        rs1 += __shfl_xor_sync(0xffffffffu, rs1, 1);
        rs1 += __shfl_xor_sync(0xffffffffu, rs1, 2);
        l0 = l0 * corr0 + rs0;
        l1 = l1 * corr1 + rs1;

        #pragma unroll
        for (int ni = 0; ni < 8; ++ni) {
            o[ni][0] *= corr0; o[ni][1] *= corr0;
            o[ni][2] *= corr1; o[ni][3] *= corr1;
        }
        __syncwarp();

        // O += P V   (A = P rows of this warp, B = Vt)
        #pragma unroll
        for (int jj = 0; jj < 4; ++jj) {
            const int fc = (qq * 4 + jj * 16) ^ swzg;
            float4 plo = *reinterpret_cast<const float4*>(&Ks[wid*16 + g    ][fc]);
            float4 phi = *reinterpret_cast<const float4*>(&Ks[wid*16 + g + 8][fc]);
            uint32_t a0[4] = {fu(plo.x), fu(phi.x), fu(plo.y), fu(phi.y)};
            uint32_t a1[4] = {fu(plo.z), fu(phi.z), fu(plo.w), fu(phi.w)};
            #pragma unroll
            for (int ni = 0; ni < 8; ++ni) {
                float4 b4 = *reinterpret_cast<const float4*>(&Vt[ni * 8 + g][fc]);
                uint32_t b0[2] = {fu(b4.x), fu(b4.y)};
                uint32_t b1[2] = {fu(b4.z), fu(b4.w)};
                mma_tf32(o[ni], a0, b0);
                mma_tf32(o[ni], a1, b1);
            }
        }
        __syncthreads();   // protect Ks/Vt before next tile load
    }

    // Write O / l  ->  g_y [b][t][h*64+d]
    const int b = bh / Hh;
    const int h = bh % Hh;
    const float inv0 = 1.f / l0;
    const float inv1 = 1.f / l1;
    const int r0 = q0 + g;
    #pragma unroll
    for (int ni = 0; ni < 8; ++ni) {
        int c = ni * 8 + 2 * qq;
        float2 v0 = make_float2(o[ni][0] * inv0, o[ni][1] * inv0);
        float2 v1 = make_float2(o[ni][2] * inv1, o[ni][3] * inv1);
        *reinterpret_cast<float2*>(&g_y[((size_t)(b * Ts + r0    )) * Cc + h * Dh + c]) = v0;
        *reinterpret_cast<float2*>(&g_y[((size_t)(b * Ts + r0 + 8)) * Cc + h * Dh + c]) = v1;
    }
}

extern "C" void kernel_launch(void* const* d_in, const int* in_sizes, int n_in,
                              void* d_out, int out_size)
{
    const float* x  = (const float*)d_in[0];
    const float* Wk = (const float*)d_in[1];
    const float* Wq = (const float*)d_in[2];
    const float* Wv = (const float*)d_in[3];
    const float* Wp = (const float*)d_in[4];
    const float* bp = (const float*)d_in[5];
    float* out = (float*)d_out;

    dim3 gridQKV(Cc / 128, MROWS / 128, 3);
    gemm_tf32<0><<<gridQKV, 256>>>(x, Wk, Wq, Wv, nullptr, nullptr);

    dim3 gridAtt(Ts / 64, Bb * Hh);
    attn_tf32<<<gridAtt, 128>>>();

    dim3 gridOut(Cc / 128, MROWS / 128);
    gemm_tf32<1><<<gridOut, 256>>>(nullptr, Wp, nullptr, nullptr, bp, out);
}

// round 4
// speedup vs baseline: 7.8648x; 2.7366x over previous
#include <cuda_runtime.h>
#include <cuda_fp16.h>
#include <cstdint>

#define Bb 2
#define Ts 2048
#define Cc 1024
#define Hh 16
#define Dh 64
#define MROWS (Bb*Ts)   // 4096
#define SCALE 0.125f
#define WELEM (Cc*Cc)

// Scratch (allocation-free rule: __device__ globals)
__device__ __align__(16) __half g_xh[MROWS*Cc];
__device__ __align__(16) __half g_wh[4*WELEM];          // Wk, Wq, Wv, Wp (fp16)
__device__ __align__(16) __half g_qh[Bb*Hh*Ts*Dh];      // [b,h,t,d], pre-scaled by 1/8
__device__ __align__(16) __half g_kh[Bb*Hh*Ts*Dh];
__device__ __align__(16) __half g_vh[Bb*Hh*Ts*Dh];
__device__ __align__(16) __half g_yh[MROWS*Cc];

__device__ __forceinline__ void cp16(uint32_t dst, const void* src) {
    asm volatile("cp.async.cg.shared.global [%0], [%1], 16;\n" :: "r"(dst), "l"(src));
}
__device__ __forceinline__ void cp_commit() { asm volatile("cp.async.commit_group;\n"); }
template<int N> __device__ __forceinline__ void cp_wait() {
    asm volatile("cp.async.wait_group %0;\n" :: "n"(N));
}
__device__ __forceinline__ void ldsm4(uint32_t& r0, uint32_t& r1, uint32_t& r2, uint32_t& r3, uint32_t a) {
    asm volatile("ldmatrix.sync.aligned.m8n8.x4.shared.b16 {%0,%1,%2,%3}, [%4];\n"
                 : "=r"(r0), "=r"(r1), "=r"(r2), "=r"(r3) : "r"(a));
}
__device__ __forceinline__ void ldsm4t(uint32_t& r0, uint32_t& r1, uint32_t& r2, uint32_t& r3, uint32_t a) {
    asm volatile("ldmatrix.sync.aligned.m8n8.x4.trans.shared.b16 {%0,%1,%2,%3}, [%4];\n"
                 : "=r"(r0), "=r"(r1), "=r"(r2), "=r"(r3) : "r"(a));
}
__device__ __forceinline__ void mma16816(float* c, const uint32_t* a, uint32_t b0, uint32_t b1) {
    asm volatile("mma.sync.aligned.m16n8k16.row.col.f32.f16.f16.f32 "
                 "{%0,%1,%2,%3}, {%4,%5,%6,%7}, {%8,%9}, {%0,%1,%2,%3};\n"
                 : "+f"(c[0]), "+f"(c[1]), "+f"(c[2]), "+f"(c[3])
                 : "r"(a[0]), "r"(a[1]), "r"(a[2]), "r"(a[3]), "r"(b0), "r"(b1));
}

// ---------------- f32 -> f16 preconversion ----------------
__global__ void f2h_kernel(const float* __restrict__ s, int which, int n8) {
    int i = blockIdx.x * blockDim.x + threadIdx.x;
    if (i >= n8) return;
    __half* d = (which == 0) ? g_xh : g_wh + (size_t)(which - 1) * WELEM;
    float4 a = reinterpret_cast<const float4*>(s)[2*i];
    float4 b = reinterpret_cast<const float4*>(s)[2*i+1];
    __half2* d2 = reinterpret_cast<__half2*>(d) + 4*i;
    d2[0] = __floats2half2_rn(a.x, a.y);
    d2[1] = __floats2half2_rn(a.z, a.w);
    d2[2] = __floats2half2_rn(b.x, b.y);
    d2[3] = __floats2half2_rn(b.z, b.w);
}

// ---------------- fp16 GEMM: out = A[M,K] @ W[N,K]^T ----------------
// Block 128x128, BK=32 halves, 2-stage cp.async, 8 warps 2(M)x4(N), warp 64x32.
// smem row = 32 halves (64B = 4 chunks of 16B); chunk swizzle: c ^ ((row>>1)&3).
template<int MODE>
__global__ __launch_bounds__(256, 2)
void gemm_h(const float* __restrict__ bias, float* __restrict__ out_final)
{
    const __half* A = (MODE == 0) ? g_xh : g_yh;
    const __half* W = g_wh + (size_t)((MODE == 0) ? blockIdx.z : 3) * WELEM;

    __shared__ __align__(16) __half Asm[2][4096];
    __shared__ __align__(16) __half Bsm[2][4096];

    const int tid = threadIdx.x, lane = tid & 31, warp = tid >> 5;
    const int wm = warp & 1, wn = warp >> 1;
    const int g = lane >> 2, qq = lane & 3;
    const int bm = blockIdx.y * 128, bn = blockIdx.x * 128;

    const uint32_t sA = (uint32_t)__cvta_generic_to_shared(&Asm[0][0]);
    const uint32_t sB = (uint32_t)__cvta_generic_to_shared(&Bsm[0][0]);

    // fragment address constants (bytes; row stride 64B)
    const int lr8  = (lane & 7) + (lane & 8);      // 0..15
    const int lq   = lane >> 4;                    // 0..1
    const int swzA = (lr8 >> 1) & 3;
    const uint32_t aBase = sA + (uint32_t)(wm*64 + lr8) * 64;
    const int rB   = (lane & 7);
    const int swzB = (rB >> 1) & 3;
    const int cB   = lane >> 3;                    // 0..3
    const uint32_t bBase = sB + (uint32_t)(wn*32 + rB) * 64 + (uint32_t)((cB ^ swzB) << 4);

    float acc[4][4][4];
    #pragma unroll
    for (int i = 0; i < 4; ++i)
        #pragma unroll
        for (int j = 0; j < 4; ++j)
            #pragma unroll
            for (int r = 0; r < 4; ++r) acc[i][j][r] = 0.f;

    // loader
    const int ldr = tid >> 2, ldc = tid & 3;
    const int ldr2 = (tid + 256) >> 2, ldc2 = (tid + 256) & 3;
    const uint32_t dof1 = (uint32_t)(ldr*32  + ((ldc  ^ ((ldr >>1)&3)) << 3)) * 2;
    const uint32_t dof2 = (uint32_t)(ldr2*32 + ((ldc2 ^ ((ldr2>>1)&3)) << 3)) * 2;

    #define G_LOAD(st, kt) do {                                              \
        uint32_t so = (uint32_t)(st) * 8192;                                  \
        cp16(sA + so + dof1, A + (size_t)(bm + ldr )*Cc + (kt) + ldc *8);     \
        cp16(sA + so + dof2, A + (size_t)(bm + ldr2)*Cc + (kt) + ldc2*8);     \
        cp16(sB + so + dof1, W + (size_t)(bn + ldr )*Cc + (kt) + ldc *8);     \
        cp16(sB + so + dof2, W + (size_t)(bn + ldr2)*Cc + (kt) + ldc2*8);     \
    } while (0)

    G_LOAD(0, 0);
    cp_commit();

    const int NIT = Cc / 32;
    for (int it = 0; it < NIT; ++it) {
        if (it + 1 < NIT) { G_LOAD((it+1)&1, (it+1)*32); cp_commit(); cp_wait<1>(); }
        else              { cp_wait<0>(); }
        __syncthreads();

        const uint32_t so = (uint32_t)(it & 1) * 8192;
        uint32_t bf[4][4];
        #pragma unroll
        for (int ni = 0; ni < 4; ++ni)
            ldsm4(bf[ni][0], bf[ni][1], bf[ni][2], bf[ni][3], bBase + so + (uint32_t)(ni*8*64));
        #pragma unroll
        for (int mi = 0; mi < 4; ++mi) {
            uint32_t a0[4], a1[4];
            ldsm4(a0[0], a0[1], a0[2], a0[3], aBase + so + (uint32_t)(mi*16*64) + (uint32_t)(((0 + lq) ^ swzA) << 4));
            ldsm4(a1[0], a1[1], a1[2], a1[3], aBase + so + (uint32_t)(mi*16*64) + (uint32_t)(((2 + lq) ^ swzA) << 4));
            #pragma unroll
            for (int ni = 0; ni < 4; ++ni) {
                mma16816(acc[mi][ni], a0, bf[ni][0], bf[ni][1]);
                mma16816(acc[mi][ni], a1, bf[ni][2], bf[ni][3]);
            }
        }
        __syncthreads();
    }
    #undef G_LOAD

    // Epilogue
    if (MODE == 0) {
        __half* outp = (blockIdx.z == 0) ? g_kh : (blockIdx.z == 1 ? g_qh : g_vh);
        const float sc = (blockIdx.z == 1) ? SCALE : 1.f;
        #pragma unroll
        for (int mi = 0; mi < 4; ++mi) {
            int r0 = bm + wm*64 + mi*16 + g;
            int b0 = r0 >> 11;
            int t0 = r0 & (Ts - 1);
            int t1 = (r0 + 8) & (Ts - 1);
            #pragma unroll
            for (int ni = 0; ni < 4; ++ni) {
                int c  = bn + wn*32 + ni*8 + 2*qq;
                int hh = c >> 6, dd = c & (Dh - 1);
                size_t base = ((size_t)(b0*Hh + hh)) * Ts;
                *reinterpret_cast<__half2*>(&outp[(base + t0)*Dh + dd]) =
                    __floats2half2_rn(acc[mi][ni][0]*sc, acc[mi][ni][1]*sc);
                *reinterpret_cast<__half2*>(&outp[(base + t1)*Dh + dd]) =
                    __floats2half2_rn(acc[mi][ni][2]*sc, acc[mi][ni][3]*sc);
            }
        }
    } else {
        #pragma unroll
        for (int mi = 0; mi < 4; ++mi) {
            int r0 = bm + wm*64 + mi*16 + g;
            #pragma unroll
            for (int ni = 0; ni < 4; ++ni) {
                int c = bn + wn*32 + ni*8 + 2*qq;
                float2 bb = *reinterpret_cast<const float2*>(&bias[c]);
                *reinterpret_cast<float2*>(&out_final[(size_t)r0 * Cc + c]) =
                    make_float2(acc[mi][ni][0] + bb.x, acc[mi][ni][1] + bb.y);
                *reinterpret_cast<float2*>(&out_final[(size_t)(r0 + 8) * Cc + c]) =
                    make_float2(acc[mi][ni][2] + bb.x, acc[mi][ni][3] + bb.y);
            }
        }
    }
}

// ---------------- Flash attention: fp16 mma + ldmatrix + cp.async ----------------
// CTA 128 thr / 4 warps; q-tile 64 (16 rows per warp); KV tiles 64, 2-stage.
// K/V smem rows = 64 halves (128B, 8 chunks); swizzle c ^ (row&7). P private buffer.
__global__ __launch_bounds__(128)
void attn_h()
{
    const int bh = blockIdx.y, qt = blockIdx.x;
    const int tid = threadIdx.x, lane = tid & 31, wid = tid >> 5;
    const int g = lane >> 2, qq = lane & 3;

    const __half* qh = g_qh + (size_t)bh * Ts * Dh;
    const __half* kh = g_kh + (size_t)bh * Ts * Dh;
    const __half* vh = g_vh + (size_t)bh * Ts * Dh;

    __shared__ __align__(16) __half Ksm[2][4096];
    __shared__ __align__(16) __half Vsm[2][4096];
    __shared__ __align__(16) __half Psm[4096];

    const uint32_t sK = (uint32_t)__cvta_generic_to_shared(&Ksm[0][0]);
    const uint32_t sV = (uint32_t)__cvta_generic_to_shared(&Vsm[0][0]);
    const uint32_t sP = (uint32_t)__cvta_generic_to_shared(&Psm[0]);

    const int q0 = qt*64 + wid*16;

    // loader constants: 512 chunks per matrix, 4 per thread
    const int l7 = lane & 7;
    int lr[4], lc[4];
    uint32_t dof[4];
    #pragma unroll
    for (int m = 0; m < 4; ++m) {
        int id = tid + 128*m;
        lr[m] = id >> 3; lc[m] = id & 7;
        dof[m] = (uint32_t)(lr[m]*64 + ((lc[m] ^ (lr[m]&7)) << 3)) * 2;
    }
    #define KV_LOAD(st, kt) do {                                              \
        uint32_t so = (uint32_t)(st) * 8192;                                   \
        _Pragma("unroll")                                                      \
        for (int m = 0; m < 4; ++m) {                                          \
            cp16(sK + so + dof[m], kh + (size_t)((kt) + lr[m])*Dh + lc[m]*8);  \
            cp16(sV + so + dof[m], vh + (size_t)((kt) + lr[m])*Dh + lc[m]*8);  \
        }                                                                      \
    } while (0)

    KV_LOAD(0, 0);
    cp_commit();

    // Q fragments from global fp16 (q already scaled by 1/8)
    uint32_t qf[4][4];
    #pragma unroll
    for (int ks = 0; ks < 4; ++ks) {
        const __half* p0 = qh + (size_t)(q0 + g    )*Dh + ks*16 + 2*qq;
        const __half* p1 = qh + (size_t)(q0 + g + 8)*Dh + ks*16 + 2*qq;
        qf[ks][0] = *reinterpret_cast<const uint32_t*>(p0);
        qf[ks][1] = *reinterpret_cast<const uint32_t*>(p1);
        qf[ks][2] = *reinterpret_cast<const uint32_t*>(p0 + 8);
        qf[ks][3] = *reinterpret_cast<const uint32_t*>(p1 + 8);
    }

    float o[8][4];
    #pragma unroll
    for (int ni = 0; ni < 8; ++ni)
        #pragma unroll
        for (int r = 0; r < 4; ++r) o[ni][r] = 0.f;
    float m0 = -1e30f, m1 = -1e30f, l0 = 0.f, l1 = 0.f;

    // per-thread LDSM address constants
    const int lr8 = (lane & 7) + (lane & 8);
    const int lq  = lane >> 4;
    const uint32_t kBase = sK + (uint32_t)l7 * 128;                            // + ni*8*128 + chunk
    const uint32_t vBase = sV + (uint32_t)((lane >> 3)*8 + l7) * 128;          // + j*32*128 + (ni^l7)<<4
    const uint32_t pBase = sP + (uint32_t)(wid*16 + lr8) * 128;                // + ((2ks+lq)^(lr8&7))<<4
    const int kChunk = lane >> 3;                                              // 0..3

    const int NIT = Ts / 64;
    for (int it = 0; it < NIT; ++it) {
        if (it + 1 < NIT) { KV_LOAD((it+1)&1, (it+1)*64); cp_commit(); cp_wait<1>(); }
        else              { cp_wait<0>(); }
        __syncthreads();

        const uint32_t so = (uint32_t)(it & 1) * 8192;

        // S = Q K^T  (warp: 16 x 64)
        float s[8][4];
        #pragma unroll
        for (int ni = 0; ni < 8; ++ni) {
            #pragma unroll
            for (int r = 0; r < 4; ++r) s[ni][r] = 0.f;
            uint32_t b0,b1,b2,b3,b4,b5,b6,b7;
            uint32_t base = kBase + so + (uint32_t)(ni*8*128);
            ldsm4(b0,b1,b2,b3, base + (uint32_t)(((kChunk    ) ^ l7) << 4));
            ldsm4(b4,b5,b6,b7, base + (uint32_t)(((kChunk + 4) ^ l7) << 4));
            mma16816(s[ni], qf[0], b0, b1);
            mma16816(s[ni], qf[1], b2, b3);
            mma16816(s[ni], qf[2], b4, b5);
            mma16816(s[ni], qf[3], b6, b7);
        }

        // Online softmax
        float mt0 = m0, mt1 = m1;
        #pragma unroll
        for (int ni = 0; ni < 8; ++ni) {
            mt0 = fmaxf(mt0, fmaxf(s[ni][0], s[ni][1]));
            mt1 = fmaxf(mt1, fmaxf(s[ni][2], s[ni][3]));
        }
        mt0 = fmaxf(mt0, __shfl_xor_sync(0xffffffffu, mt0, 1));
        mt0 = fmaxf(mt0, __shfl_xor_sync(0xffffffffu, mt0, 2));
        mt1 = fmaxf(mt1, __shfl_xor_sync(0xffffffffu, mt1, 1));
        mt1 = fmaxf(mt1, __shfl_xor_sync(0xffffffffu, mt1, 2));
        float corr0 = __expf(m0 - mt0);
        float corr1 = __expf(m1 - mt1);
        m0 = mt0; m1 = mt1;

        float rs0 = 0.f, rs1 = 0.f;
        #pragma unroll
        for (int ni = 0; ni < 8; ++ni) {
            float p0 = __expf(s[ni][0] - m0);
            float p1 = __expf(s[ni][1] - m0);
            float p2 = __expf(s[ni][2] - m1);
            float p3 = __expf(s[ni][3] - m1);
            rs0 += p0 + p1;
            rs1 += p2 + p3;
            int idx0 = (wid*16 + g    )*64 + ((ni ^ g) << 3) + 2*qq;
            int idx1 = (wid*16 + g + 8)*64 + ((ni ^ g) << 3) + 2*qq;
            *reinterpret_cast<__half2*>(&Psm[idx0]) = __floats2half2_rn(p0, p1);
            *reinterpret_cast<__half2*>(&Psm[idx1]) = __floats2half2_rn(p2, p3);
        }
        rs0 += __shfl_xor_sync(0xffffffffu, rs0, 1);
        rs0 += __shfl_xor_sync(0xffffffffu, rs0, 2);
        rs1 += __shfl_xor_sync(0xffffffffu, rs1, 1);
        rs1 += __shfl_xor_sync(0xffffffffu, rs1, 2);
        l0 = l0 * corr0 + rs0;
        l1 = l1 * corr1 + rs1;

        #pragma unroll
        for (int ni = 0; ni < 8; ++ni) {
            o[ni][0] *= corr0; o[ni][1] *= corr0;
            o[ni][2] *= corr1; o[ni][3] *= corr1;
        }
        __syncwarp();

        // P fragments (A) from smem
        uint32_t ap[4][4];
        #pragma unroll
        for (int ks = 0; ks < 4; ++ks)
            ldsm4(ap[ks][0], ap[ks][1], ap[ks][2], ap[ks][3],
                  pBase + (uint32_t)((((2*ks + lq)) ^ (lr8 & 7)) << 4));

        // O += P V  (V via ldmatrix.trans)
        #pragma unroll
        for (int ni = 0; ni < 8; ++ni) {
            uint32_t c0,c1,c2,c3,c4,c5,c6,c7;
            uint32_t vb = vBase + so + (uint32_t)((ni ^ l7) << 4);
            ldsm4t(c0,c1,c2,c3, vb);
            ldsm4t(c4,c5,c6,c7, vb + (uint32_t)(32*128));
            mma16816(o[ni], ap[0], c0, c1);
            mma16816(o[ni], ap[1], c2, c3);
            mma16816(o[ni], ap[2], c4, c5);
            mma16816(o[ni], ap[3], c6, c7);
        }
        __syncthreads();
    }
    #undef KV_LOAD

    // Write O/l -> g_yh [b][t][h*64+d] (fp16)
    const int b = bh / Hh, h = bh % Hh;
    const float inv0 = 1.f / l0, inv1 = 1.f / l1;
    const int r0 = q0 + g;
    #pragma unroll
    for (int ni = 0; ni < 8; ++ni) {
        int c = ni*8 + 2*qq;
        *reinterpret_cast<__half2*>(&g_yh[((size_t)(b*Ts + r0    ))*Cc + h*Dh + c]) =
            __floats2half2_rn(o[ni][0]*inv0, o[ni][1]*inv0);
        *reinterpret_cast<__half2*>(&g_yh[((size_t)(b*Ts + r0 + 8))*Cc + h*Dh + c]) =
            __floats2half2_rn(o[ni][2]*inv1, o[ni][3]*inv1);
    }
}

extern "C" void kernel_launch(void* const* d_in, const int* in_sizes, int n_in,
                              void* d_out, int out_size)
{
    const float* x  = (const float*)d_in[0];
    const float* Wk = (const float*)d_in[1];
    const float* Wq = (const float*)d_in[2];
    const float* Wv = (const float*)d_in[3];
    const float* Wp = (const float*)d_in[4];
    const float* bp = (const float*)d_in[5];
    float* out = (float*)d_out;

    const int nx8 = MROWS*Cc/8, nw8 = WELEM/8;
    f2h_kernel<<<(nx8 + 255)/256, 256>>>(x,  0, nx8);
    f2h_kernel<<<(nw8 + 255)/256, 256>>>(Wk, 1, nw8);
    f2h_kernel<<<(nw8 + 255)/256, 256>>>(Wq, 2, nw8);
    f2h_kernel<<<(nw8 + 255)/256, 256>>>(Wv, 3, nw8);
    f2h_kernel<<<(nw8 + 255)/256, 256>>>(Wp, 4, nw8);

    dim3 gridQKV(Cc/128, MROWS/128, 3);
    gemm_h<0><<<gridQKV, 256>>>(nullptr, nullptr);

    dim3 gridAtt(Ts/64, Bb*Hh);
    attn_h<<<gridAtt, 128>>>();

    dim3 gridOut(Cc/128, MROWS/128, 1);
    gemm_h<1><<<gridOut, 256>>>(bp, out);
}